// round 9
// baseline (speedup 1.0000x reference)
#include <cuda_runtime.h>
#include <cuda_fp16.h>
#include <cstdint>

#define TOKENS 16384
#define DIMS   128
#define SLOTS  64

// ---------------- device globals ---------------------------------------------
__device__ __align__(16) float g_C[DIMS * SLOTS];        // C[d][m], pre-scaled
__device__ __align__(16) float g_d0[SLOTS];               // bias, pre-scaled
__device__ __align__(16) unsigned g_opsH[SLOTS * DIMS * 64]; // fp16 ops, swizzled (2MB)

// ---------------- helpers ----------------------------------------------------
__device__ __forceinline__ uint32_t smem_u32(const void* p) {
    uint32_t a;
    asm("{ .reg .u64 t; cvta.to.shared.u64 t, %1; cvt.u32.u64 %0, t; }" : "=r"(a) : "l"(p));
    return a;
}
__device__ __forceinline__ unsigned packh2(float lo, float hi) {
    unsigned u;
    asm("{ .reg .f16 l, h; cvt.rn.f16.f32 l, %1; cvt.rn.f16.f32 h, %2; mov.b32 %0, {l, h}; }"
        : "=r"(u) : "f"(lo), "f"(hi));
    return u;
}
__device__ __forceinline__ unsigned hmul2(unsigned a, unsigned b) {
    unsigned r; asm("mul.rn.f16x2 %0, %1, %2;" : "=r"(r) : "r"(a), "r"(b)); return r;
}
__device__ __forceinline__ void ldsm4(unsigned* r, uint32_t addr) {
    asm volatile("ldmatrix.sync.aligned.m8n8.x4.shared.b16 {%0,%1,%2,%3}, [%4];"
                 : "=r"(r[0]), "=r"(r[1]), "=r"(r[2]), "=r"(r[3]) : "r"(addr));
}
__device__ __forceinline__ void mma16816(float* c, const unsigned* a, unsigned b0, unsigned b1) {
    asm volatile(
        "mma.sync.aligned.m16n8k16.row.col.f32.f16.f16.f32 "
        "{%0,%1,%2,%3}, {%4,%5,%6,%7}, {%8,%9}, {%0,%1,%2,%3};"
        : "+f"(c[0]), "+f"(c[1]), "+f"(c[2]), "+f"(c[3])
        : "r"(a[0]), "r"(a[1]), "r"(a[2]), "r"(a[3]), "r"(b0), "r"(b1));
}
__device__ __forceinline__ void cpasync16(uint32_t dst, const void* src) {
    asm volatile("cp.async.cg.shared.global [%0], [%1], 16;" :: "r"(dst), "l"(src) : "memory");
}

// ---------------- kernel A: ops->fp16 swizzled image + C/d0 precompute -------
__global__ void kA(const float* __restrict__ ops, const float* __restrict__ Wq,
                   const float* __restrict__ bq, const float* __restrict__ MK) {
    __shared__ float mk[128];
    __shared__ float part[128];
    const int b = blockIdx.x, tid = threadIdx.x;
    if (b < 256) {
#pragma unroll
        for (int i = 0; i < 2; i++) {
            int idx = b * 512 + i * 256 + tid;       // 16B-chunk id, 131072 total
            int m = idx >> 11, c = idx & 2047;
            int d = c >> 4, ch = c & 15;
            const float4* s = (const float4*)(ops + m * 16384 + d * 128 + ch * 8);
            float4 v0 = s[0], v1 = s[1];
            uint4 o;
            o.x = packh2(v0.x, v0.y); o.y = packh2(v0.z, v0.w);
            o.z = packh2(v1.x, v1.y); o.w = packh2(v1.z, v1.w);
            unsigned dst = (unsigned)m * 8192u + (unsigned)d * 64u
                         + (unsigned)((ch ^ (d & 7)) << 2);   // u32 units
            *(uint4*)(g_opsH + dst) = o;
        }
    } else {
        const int m = b - 256;                        // 0..63
        if (tid < 128) mk[tid] = MK[m * 128 + tid];
        __syncthreads();
        const int d = tid & 127, half = tid >> 7;
        const int e0 = half * 64;
        float s = 0.f;
#pragma unroll 8
        for (int e = e0; e < e0 + 64; e++) s += Wq[e * 128 + d] * mk[e];
        if (half) part[d] = s;
        __syncthreads();
        const float inv = 0.08838834764831845f;
        if (!half) g_C[d * 64 + m] = (s + part[d]) * inv;
        if (tid == 0) {
            float s2 = 0.f;
#pragma unroll 8
            for (int e = 0; e < 128; e++) s2 += bq[e] * mk[e];
            g_d0[m] = s2 * inv;
        }
    }
}

// ---------------- kernel 2: fused attn + fp16 mma, A in registers ------------
// 296 CTAs x 256 thr, 2 CTAs/SM. CTA = ng*16 tokens (4 or 3 groups) x 128 dims.
// Warps: 2 rows x 4 cols; row r owns groups {r, r+2}; col owns 32 dims.
// A fragments (x tile) loaded ONCE into 64 persistent regs; per-slot only
// B ldsm + hmul2(attn) + mma.  SMEM: xs 16KB | AP 8KB | B dbl 2x32KB = 90112.
__global__ __launch_bounds__(256, 2) void k2_fused(const float* __restrict__ x,
                                                   float* __restrict__ out) {
    extern __shared__ __align__(16) unsigned char smraw[];
    const uint32_t XS = smem_u32(smraw);
    const uint32_t AP = XS + 16384u;
    const uint32_t BB = XS + 24576u;
    float* Cs = (float*)(smraw + 24576);            // B buf0 (32KB) during attn
    float* ls = (float*)(smraw + 24576 + 32768);    // B buf1 during attn

    const int tid = threadIdx.x, l = tid & 31, w = tid >> 5;
    const int rowi = w >> 2, wd = (w & 3) * 32;
    const int cta = blockIdx.x;
    const int ng = (cta < 136) ? 4 : 3;
    const int t0 = (cta < 136) ? cta * 64 : 8704 + (cta - 136) * 48;
    const int ntok = ng * 16;

    // ---- stage x tile: fp32 -> fp16, XOR-swizzled [t][e] ----
    for (int idx = tid; idx < ntok * 16; idx += 256) {
        int row = idx >> 4, ch = idx & 15;
        const float4* sp = (const float4*)(x + (size_t)(t0 + row) * 128 + ch * 8);
        float4 v0 = sp[0], v1 = sp[1];
        uint4 o;
        o.x = packh2(v0.x, v0.y); o.y = packh2(v0.z, v0.w);
        o.z = packh2(v1.x, v1.y); o.w = packh2(v1.z, v1.w);
        asm volatile("st.shared.v4.b32 [%0], {%1,%2,%3,%4};"
                     :: "r"(XS + (unsigned)(row * 256) + (unsigned)((ch ^ (row & 7)) << 4)),
                        "r"(o.x), "r"(o.y), "r"(o.z), "r"(o.w) : "memory");
    }
    // ---- stage C into B buf0 ----
    for (int idx = tid; idx < 2048; idx += 256)
        ((float4*)Cs)[idx] = ((const float4*)g_C)[idx];
    __syncthreads();

    // ---- logits: fp32 ----
    {
        const int t = tid >> 2, mg = tid & 3;
        if (t < ntok) {
            float acc[16];
#pragma unroll
            for (int j = 0; j < 16; j++) acc[j] = g_d0[mg * 16 + j];
            const float4* xp = (const float4*)(x + (size_t)(t0 + t) * 128);
#pragma unroll 4
            for (int d4 = 0; d4 < 32; d4++) {
                float4 xv4 = xp[d4];
                const float* cb = Cs + (d4 * 4) * 64 + mg * 16;
#pragma unroll
                for (int q = 0; q < 4; q++) {
                    float xv = (q == 0) ? xv4.x : (q == 1) ? xv4.y : (q == 2) ? xv4.z : xv4.w;
                    const float4* c4 = (const float4*)(cb + q * 64);
#pragma unroll
                    for (int j4 = 0; j4 < 4; j4++) {
                        float4 cc = c4[j4];
                        acc[j4*4+0] = fmaf(xv, cc.x, acc[j4*4+0]);
                        acc[j4*4+1] = fmaf(xv, cc.y, acc[j4*4+1]);
                        acc[j4*4+2] = fmaf(xv, cc.z, acc[j4*4+2]);
                        acc[j4*4+3] = fmaf(xv, cc.w, acc[j4*4+3]);
                    }
                }
            }
#pragma unroll
            for (int j = 0; j < 16; j++) ls[t * 65 + mg * 16 + j] = acc[j];
        }
    }
    __syncthreads();
    // ---- softmax per token ----
    if (tid < ntok) {
        float mx = -1e30f;
#pragma unroll 8
        for (int m = 0; m < 64; m++) mx = fmaxf(mx, ls[tid * 65 + m]);
        float s = 0.f;
#pragma unroll 8
        for (int m = 0; m < 64; m++) { float e = __expf(ls[tid*65+m]-mx); ls[tid*65+m] = e; s += e; }
        float iv = 1.f / s;
#pragma unroll 8
        for (int m = 0; m < 64; m++) ls[tid * 65 + m] *= iv;
    }
    __syncthreads();
    // ---- pack attn pairs (t, t+8) fp16x2 into AP [m][32] ----
    for (int idx = tid; idx < 64 * 32; idx += 256) {
        int m = idx >> 5, p = idx & 31;
        int g = p >> 3;
        if (g < ng) {
            int tl = g * 16 + (p & 7);
            unsigned u = packh2(ls[tl * 65 + m], ls[(tl + 8) * 65 + m]);
            asm volatile("st.shared.b32 [%0], %1;" :: "r"(AP + (unsigned)idx * 4), "r"(u) : "memory");
        }
    }
    __syncthreads();   // ls/Cs dead; B buffers free

    // ---- hoist A fragments into persistent registers (slot-invariant) ----
    unsigned Areg[2][8][4];
    {
        const int r_off = l & 15;
#pragma unroll
        for (int j = 0; j < 2; j++) {
            const int g = rowi + 2 * j;
            if (g < ng) {
#pragma unroll
                for (int ks = 0; ks < 8; ks++) {
                    int chA = ks * 2 + (l >> 4);
                    int row = g * 16 + r_off;
                    uint32_t addr = XS + row * 256 + ((chA ^ (r_off & 7)) << 4);
                    ldsm4(Areg[j][ks], addr);
                }
            }
        }
    }

    // ---- prologue: B(0) into buf0 ----
#pragma unroll
    for (int i = 0; i < 8; i++) {
        int idx = tid + i * 256;
        cpasync16(BB + idx * 16, (const char*)g_opsH + idx * 16);
    }
    asm volatile("cp.async.commit_group;" ::: "memory");

    float acc[2][4][4] = {};

    for (int m = 0; m < 64; m++) {
        asm volatile("cp.async.wait_group 0;" ::: "memory");
        __syncthreads();
        if (m < 63) {
            const char* src = (const char*)g_opsH + (size_t)(m + 1) * 32768;
            uint32_t dst = BB + (unsigned)((m + 1) & 1) * 32768u;
#pragma unroll
            for (int i = 0; i < 8; i++) {
                int idx = tid + i * 256;
                cpasync16(dst + idx * 16, src + idx * 16);
            }
            asm volatile("cp.async.commit_group;" ::: "memory");
        }

        // attn splats for this slot (per owned group)
        unsigned lo2[2], hi2[2];
#pragma unroll
        for (int j = 0; j < 2; j++) {
            int g = rowi + 2 * j;
            if (g < ng) {
                unsigned pu;
                asm volatile("ld.shared.b32 %0, [%1];"
                             : "=r"(pu) : "r"(AP + (unsigned)(m * 32 + g * 8 + (l >> 2)) * 4));
                asm("prmt.b32 %0, %1, %1, 0x1010;" : "=r"(lo2[j]) : "r"(pu));
                asm("prmt.b32 %0, %1, %1, 0x3232;" : "=r"(hi2[j]) : "r"(pu));
            }
        }

        const uint32_t Bb = BB + (unsigned)(m & 1) * 32768u;
#pragma unroll
        for (int ks = 0; ks < 8; ks++) {
            const int c0 = ks * 2;
            unsigned bf[2][4];
            {
                int n_off = ((l >> 4) << 3) + (l & 7);
                int chB = c0 + ((l >> 3) & 1);
#pragma unroll
                for (int np = 0; np < 2; np++) {
                    int row = wd + np * 16 + n_off;
                    uint32_t addr = Bb + row * 256 + ((chB ^ (row & 7)) << 4);
                    ldsm4(bf[np], addr);
                }
            }
#pragma unroll
            for (int j = 0; j < 2; j++) {
                int g = rowi + 2 * j;
                if (g < ng) {
                    unsigned t[4];
                    t[0] = hmul2(Areg[j][ks][0], lo2[j]);
                    t[1] = hmul2(Areg[j][ks][1], hi2[j]);
                    t[2] = hmul2(Areg[j][ks][2], lo2[j]);
                    t[3] = hmul2(Areg[j][ks][3], hi2[j]);
#pragma unroll
                    for (int nt = 0; nt < 4; nt++)
                        mma16816(acc[j][nt], t, bf[nt >> 1][(nt & 1) * 2],
                                 bf[nt >> 1][(nt & 1) * 2 + 1]);
                }
            }
        }
    }

    // ---- writeback ----
#pragma unroll
    for (int j = 0; j < 2; j++) {
        int g = rowi + 2 * j;
        if (g < ng) {
            int row = t0 + g * 16 + (l >> 2);
#pragma unroll
            for (int nt = 0; nt < 4; nt++) {
                int col = wd + nt * 8 + (l & 3) * 2;
                *(float2*)(out + (size_t)row * 128 + col) =
                    make_float2(acc[j][nt][0], acc[j][nt][1]);
                *(float2*)(out + (size_t)(row + 8) * 128 + col) =
                    make_float2(acc[j][nt][2], acc[j][nt][3]);
            }
        }
    }
}

// ---------------------------------------------------------------------------
extern "C" void kernel_launch(void* const* d_in, const int* in_sizes, int n_in,
                              void* d_out, int out_size) {
    const float* x   = (const float*)d_in[0];   // [4,4096,128]
    const float* MK  = (const float*)d_in[1];   // [64,128]
    const float* ops = (const float*)d_in[2];   // [64,128,128]
    const float* Wq  = (const float*)d_in[3];   // [128,128]
    const float* bq  = (const float*)d_in[4];   // [128]
    float* out = (float*)d_out;

    const int smem2 = 90112;
    cudaFuncSetAttribute(k2_fused, cudaFuncAttributeMaxDynamicSharedMemorySize, smem2);

    kA<<<320, 256>>>(ops, Wq, bq, MK);
    k2_fused<<<296, 256, smem2>>>(x, out);
}

// round 11
// speedup vs baseline: 1.0580x; 1.0580x over previous
#include <cuda_runtime.h>
#include <cuda_fp16.h>
#include <cstdint>

#define TOKENS 16384
#define DIMS   128
#define SLOTS  64

// ---------------- device globals ---------------------------------------------
__device__ __align__(16) float g_C[DIMS * SLOTS];        // C[d][m], pre-scaled
__device__ __align__(16) float g_d0[SLOTS];               // bias, pre-scaled
__device__ __align__(16) unsigned g_opsH[SLOTS * DIMS * 64]; // fp16 ops, swizzled (2MB)

// ---------------- helpers ----------------------------------------------------
__device__ __forceinline__ uint32_t smem_u32(const void* p) {
    uint32_t a;
    asm("{ .reg .u64 t; cvta.to.shared.u64 t, %1; cvt.u32.u64 %0, t; }" : "=r"(a) : "l"(p));
    return a;
}
__device__ __forceinline__ unsigned packh2(float lo, float hi) {
    unsigned u;
    asm("{ .reg .f16 l, h; cvt.rn.f16.f32 l, %1; cvt.rn.f16.f32 h, %2; mov.b32 %0, {l, h}; }"
        : "=r"(u) : "f"(lo), "f"(hi));
    return u;
}
__device__ __forceinline__ unsigned hmul2(unsigned a, unsigned b) {
    unsigned r; asm("mul.rn.f16x2 %0, %1, %2;" : "=r"(r) : "r"(a), "r"(b)); return r;
}
__device__ __forceinline__ void ldsm4(unsigned* r, uint32_t addr) {
    asm volatile("ldmatrix.sync.aligned.m8n8.x4.shared.b16 {%0,%1,%2,%3}, [%4];"
                 : "=r"(r[0]), "=r"(r[1]), "=r"(r[2]), "=r"(r[3]) : "r"(addr));
}
__device__ __forceinline__ void mma16816(float* c, const unsigned* a, unsigned b0, unsigned b1) {
    asm volatile(
        "mma.sync.aligned.m16n8k16.row.col.f32.f16.f16.f32 "
        "{%0,%1,%2,%3}, {%4,%5,%6,%7}, {%8,%9}, {%0,%1,%2,%3};"
        : "+f"(c[0]), "+f"(c[1]), "+f"(c[2]), "+f"(c[3])
        : "r"(a[0]), "r"(a[1]), "r"(a[2]), "r"(a[3]), "r"(b0), "r"(b1));
}
__device__ __forceinline__ void cpasync16(uint32_t dst, const void* src) {
    asm volatile("cp.async.cg.shared.global [%0], [%1], 16;" :: "r"(dst), "l"(src) : "memory");
}

// ---------------- kernel A: ops->fp16 swizzled image + C/d0 precompute -------
// blocks 0..511: convert ops (256 chunks each); blocks 512..575: C[:,m].
__global__ void kA(const float* __restrict__ ops, const float* __restrict__ Wq,
                   const float* __restrict__ bq, const float* __restrict__ MK) {
    __shared__ float mk[128];
    __shared__ float part[128];
    const int b = blockIdx.x, tid = threadIdx.x;
    if (b < 512) {
        int idx = b * 256 + tid;                 // 16B-chunk id, 131072 total
        int m = idx >> 11, c = idx & 2047;
        int d = c >> 4, ch = c & 15;
        const float4* s = (const float4*)(ops + m * 16384 + d * 128 + ch * 8);
        float4 v0 = s[0], v1 = s[1];
        uint4 o;
        o.x = packh2(v0.x, v0.y); o.y = packh2(v0.z, v0.w);
        o.z = packh2(v1.x, v1.y); o.w = packh2(v1.z, v1.w);
        unsigned dst = (unsigned)m * 8192u + (unsigned)d * 64u
                     + (unsigned)((ch ^ (d & 7)) << 2);   // u32 units
        *(uint4*)(g_opsH + dst) = o;
    } else {
        const int m = b - 512;                   // 0..63
        if (tid < 128) mk[tid] = MK[m * 128 + tid];
        __syncthreads();
        const int d = tid & 127, half = tid >> 7;
        const int e0 = half * 64;
        float s = 0.f;
#pragma unroll 8
        for (int e = e0; e < e0 + 64; e++) s += Wq[e * 128 + d] * mk[e];
        if (half) part[d] = s;
        __syncthreads();
        const float inv = 0.08838834764831845f;
        if (!half) g_C[d * 64 + m] = (s + part[d]) * inv;
        if (tid == 0) {
            float s2 = 0.f;
#pragma unroll 8
            for (int e = 0; e < 128; e++) s2 += bq[e] * mk[e];
            g_d0[m] = s2 * inv;
        }
    }
}

// ---------------- kernel 2: fused attn + fp16 mma -----------------------------
// 148 CTAs x 512 thr (1/SM). CTA = ng*16 tokens (ng=7 for cta<136 else 6) x 128.
// Warps 4 rows x 4 cols; row r owns groups {r, r+4}; col owns 32 dims.
// A fragments hoisted to persistent regs; B via triple-buffered cp.async ring.
// SMEM map (112640 B):
//   AP   [0, 14336)          attn fp16x2 pairs (live whole kernel)
//   ring [14336, 112640)     3 x 32KB B buffers (mainloop)
//   init-phase overlays: XS = [14336, 43008) x tile;
//                        Cs = [47104, 79872) 32KB C matrix;
//                        ls = [79872, 108992) logits (112x65 f32).
__global__ __launch_bounds__(512, 1) void k2_fused(const float* __restrict__ x,
                                                   float* __restrict__ out) {
    extern __shared__ __align__(16) unsigned char smraw[];
    const uint32_t SB = smem_u32(smraw);
    const uint32_t AP = SB;                       // 14336 B
    const uint32_t BB = SB + 14336u;              // ring base
    const uint32_t XS = BB;                       // x tile (init phase, 28KB)
    float* Cs = (float*)(smraw + 47104);          // 32KB (init phase)
    float* ls = (float*)(smraw + 79872);          // 29120 B (init phase)

    const int tid = threadIdx.x, l = tid & 31, w = tid >> 5;
    const int rowi = w >> 2, wd = (w & 3) * 32;
    const int cta = blockIdx.x;
    const int ng = (cta < 136) ? 7 : 6;
    const int t0 = (cta < 136) ? cta * 112 : 15232 + (cta - 136) * 96;
    const int ntok = ng * 16;

    // ---- stage x tile: fp32 -> fp16, XOR-swizzled [t][e] ----
    for (int idx = tid; idx < ntok * 16; idx += 512) {
        int row = idx >> 4, ch = idx & 15;
        const float4* sp = (const float4*)(x + (size_t)(t0 + row) * 128 + ch * 8);
        float4 v0 = sp[0], v1 = sp[1];
        uint4 o;
        o.x = packh2(v0.x, v0.y); o.y = packh2(v0.z, v0.w);
        o.z = packh2(v1.x, v1.y); o.w = packh2(v1.z, v1.w);
        asm volatile("st.shared.v4.b32 [%0], {%1,%2,%3,%4};"
                     :: "r"(XS + (unsigned)(row * 256) + (unsigned)((ch ^ (row & 7)) << 4)),
                        "r"(o.x), "r"(o.y), "r"(o.z), "r"(o.w) : "memory");
    }
    // ---- stage C (32 KB) ----
    for (int idx = tid; idx < 2048; idx += 512)
        ((float4*)Cs)[idx] = ((const float4*)g_C)[idx];
    __syncthreads();

    // ---- logits: fp32 (x from gmem, L2-hot) ----
    {
        const int t = tid >> 2, mg = tid & 3;
        if (t < ntok) {
            float acc[16];
#pragma unroll
            for (int j = 0; j < 16; j++) acc[j] = g_d0[mg * 16 + j];
            const float4* xp = (const float4*)(x + (size_t)(t0 + t) * 128);
#pragma unroll 4
            for (int d4 = 0; d4 < 32; d4++) {
                float4 xv4 = xp[d4];
                const float* cb = Cs + (d4 * 4) * 64 + mg * 16;
#pragma unroll
                for (int q = 0; q < 4; q++) {
                    float xv = (q == 0) ? xv4.x : (q == 1) ? xv4.y : (q == 2) ? xv4.z : xv4.w;
                    const float4* c4 = (const float4*)(cb + q * 64);
#pragma unroll
                    for (int j4 = 0; j4 < 4; j4++) {
                        float4 cc = c4[j4];
                        acc[j4*4+0] = fmaf(xv, cc.x, acc[j4*4+0]);
                        acc[j4*4+1] = fmaf(xv, cc.y, acc[j4*4+1]);
                        acc[j4*4+2] = fmaf(xv, cc.z, acc[j4*4+2]);
                        acc[j4*4+3] = fmaf(xv, cc.w, acc[j4*4+3]);
                    }
                }
            }
#pragma unroll
            for (int j = 0; j < 16; j++) ls[t * 65 + mg * 16 + j] = acc[j];
        }
    }
    __syncthreads();
    // ---- softmax per token ----
    if (tid < ntok) {
        float mx = -1e30f;
#pragma unroll 8
        for (int m = 0; m < 64; m++) mx = fmaxf(mx, ls[tid * 65 + m]);
        float s = 0.f;
#pragma unroll 8
        for (int m = 0; m < 64; m++) { float e = __expf(ls[tid*65+m]-mx); ls[tid*65+m] = e; s += e; }
        float iv = 1.f / s;
#pragma unroll 8
        for (int m = 0; m < 64; m++) ls[tid * 65 + m] *= iv;
    }
    __syncthreads();
    // ---- pack attn pairs (t, t+8) fp16x2 into AP [m][56] ----
    for (int idx = tid; idx < 64 * 56; idx += 512) {
        int m = idx / 56, p = idx - m * 56;
        int g = p >> 3;
        if (g < ng) {
            int tl = g * 16 + (p & 7);
            unsigned u = packh2(ls[tl * 65 + m], ls[(tl + 8) * 65 + m]);
            asm volatile("st.shared.b32 [%0], %1;" :: "r"(AP + (unsigned)idx * 4), "r"(u) : "memory");
        }
    }
    // ---- hoist A fragments into persistent regs (xs still intact) ----
    unsigned Areg[2][8][4];
    {
        const int r_off = l & 15;
#pragma unroll
        for (int j = 0; j < 2; j++) {
            const int g = rowi + 4 * j;
            if (g < ng) {
#pragma unroll
                for (int ks = 0; ks < 8; ks++) {
                    int chA = ks * 2 + (l >> 4);
                    int row = g * 16 + r_off;
                    uint32_t addr = XS + row * 256 + ((chA ^ (r_off & 7)) << 4);
                    ldsm4(Areg[j][ks], addr);
                }
            }
        }
    }
    __syncthreads();   // xs/Cs/ls dead -> ring usable

    // ---- prologue: B(0), B(1) into ring ----
#pragma unroll
    for (int i = 0; i < 4; i++) {
        int idx = tid + i * 512;
        cpasync16(BB + idx * 16, (const char*)g_opsH + idx * 16);
    }
    asm volatile("cp.async.commit_group;" ::: "memory");
#pragma unroll
    for (int i = 0; i < 4; i++) {
        int idx = tid + i * 512;
        cpasync16(BB + 32768u + idx * 16, (const char*)g_opsH + 32768 + idx * 16);
    }
    asm volatile("cp.async.commit_group;" ::: "memory");

    float acc[2][4][4] = {};

    for (int m = 0; m < 64; m++) {
        if (m == 63) { asm volatile("cp.async.wait_group 0;" ::: "memory"); }
        else         { asm volatile("cp.async.wait_group 1;" ::: "memory"); }
        __syncthreads();
        if (m + 2 < 64) {
            const char* src = (const char*)g_opsH + (size_t)(m + 2) * 32768;
            uint32_t dst = BB + (unsigned)((m + 2) % 3) * 32768u;
#pragma unroll
            for (int i = 0; i < 4; i++) {
                int idx = tid + i * 512;
                cpasync16(dst + idx * 16, src + idx * 16);
            }
            asm volatile("cp.async.commit_group;" ::: "memory");
        }

        // attn splats for this slot (per owned group)
        unsigned lo2[2], hi2[2];
#pragma unroll
        for (int j = 0; j < 2; j++) {
            int g = rowi + 4 * j;
            if (g < ng) {
                unsigned pu;
                asm volatile("ld.shared.b32 %0, [%1];"
                             : "=r"(pu) : "r"(AP + (unsigned)(m * 56 + g * 8 + (l >> 2)) * 4));
                asm("prmt.b32 %0, %1, %1, 0x1010;" : "=r"(lo2[j]) : "r"(pu));
                asm("prmt.b32 %0, %1, %1, 0x3232;" : "=r"(hi2[j]) : "r"(pu));
            }
        }

        const uint32_t Bb = BB + (unsigned)(m % 3) * 32768u;
#pragma unroll
        for (int ks = 0; ks < 8; ks++) {
            const int c0 = ks * 2;
            unsigned bf[2][4];
            {
                int n_off = ((l >> 4) << 3) + (l & 7);
                int chB = c0 + ((l >> 3) & 1);
#pragma unroll
                for (int np = 0; np < 2; np++) {
                    int row = wd + np * 16 + n_off;
                    uint32_t addr = Bb + row * 256 + ((chB ^ (row & 7)) << 4);
                    ldsm4(bf[np], addr);
                }
            }
#pragma unroll
            for (int j = 0; j < 2; j++) {
                int g = rowi + 4 * j;
                if (g < ng) {
                    unsigned t[4];
                    t[0] = hmul2(Areg[j][ks][0], lo2[j]);
                    t[1] = hmul2(Areg[j][ks][1], hi2[j]);
                    t[2] = hmul2(Areg[j][ks][2], lo2[j]);
                    t[3] = hmul2(Areg[j][ks][3], hi2[j]);
#pragma unroll
                    for (int nt = 0; nt < 4; nt++)
                        mma16816(acc[j][nt], t, bf[nt >> 1][(nt & 1) * 2],
                                 bf[nt >> 1][(nt & 1) * 2 + 1]);
                }
            }
        }
    }

    // ---- writeback ----
#pragma unroll
    for (int j = 0; j < 2; j++) {
        int g = rowi + 4 * j;
        if (g < ng) {
            int row = t0 + g * 16 + (l >> 2);
#pragma unroll
            for (int nt = 0; nt < 4; nt++) {
                int col = wd + nt * 8 + (l & 3) * 2;
                *(float2*)(out + (size_t)row * 128 + col) =
                    make_float2(acc[j][nt][0], acc[j][nt][1]);
                *(float2*)(out + (size_t)(row + 8) * 128 + col) =
                    make_float2(acc[j][nt][2], acc[j][nt][3]);
            }
        }
    }
}

// ---------------------------------------------------------------------------
extern "C" void kernel_launch(void* const* d_in, const int* in_sizes, int n_in,
                              void* d_out, int out_size) {
    const float* x   = (const float*)d_in[0];   // [4,4096,128]
    const float* MK  = (const float*)d_in[1];   // [64,128]
    const float* ops = (const float*)d_in[2];   // [64,128,128]
    const float* Wq  = (const float*)d_in[3];   // [128,128]
    const float* bq  = (const float*)d_in[4];   // [128]
    float* out = (float*)d_out;

    const int smem2 = 112640;
    cudaFuncSetAttribute(k2_fused, cudaFuncAttributeMaxDynamicSharedMemorySize, smem2);

    kA<<<576, 256>>>(ops, Wq, bq, MK);
    k2_fused<<<148, 512, smem2>>>(x, out);
}

// round 12
// speedup vs baseline: 1.0735x; 1.0146x over previous
#include <cuda_runtime.h>
#include <cuda_fp16.h>
#include <cstdint>

#define TOKENS 16384
#define DIMS   128
#define SLOTS  64

// ---------------- device globals ---------------------------------------------
__device__ __align__(16) float g_C[DIMS * SLOTS];        // C[d][m], pre-scaled
__device__ __align__(16) float g_d0[SLOTS];               // bias, pre-scaled
__device__ __align__(16) unsigned g_opsH[SLOTS * DIMS * 64]; // fp16 ops, swizzled (2MB)

// ---------------- helpers ----------------------------------------------------
__device__ __forceinline__ uint32_t smem_u32(const void* p) {
    uint32_t a;
    asm("{ .reg .u64 t; cvta.to.shared.u64 t, %1; cvt.u32.u64 %0, t; }" : "=r"(a) : "l"(p));
    return a;
}
__device__ __forceinline__ unsigned packh2(float lo, float hi) {
    unsigned u;
    asm("{ .reg .f16 l, h; cvt.rn.f16.f32 l, %1; cvt.rn.f16.f32 h, %2; mov.b32 %0, {l, h}; }"
        : "=r"(u) : "f"(lo), "f"(hi));
    return u;
}
__device__ __forceinline__ unsigned hmul2(unsigned a, unsigned b) {
    unsigned r; asm("mul.rn.f16x2 %0, %1, %2;" : "=r"(r) : "r"(a), "r"(b)); return r;
}
__device__ __forceinline__ void ldsm4(unsigned* r, uint32_t addr) {
    asm volatile("ldmatrix.sync.aligned.m8n8.x4.shared.b16 {%0,%1,%2,%3}, [%4];"
                 : "=r"(r[0]), "=r"(r[1]), "=r"(r[2]), "=r"(r[3]) : "r"(addr));
}
__device__ __forceinline__ void mma16816(float* c, const unsigned* a, unsigned b0, unsigned b1) {
    asm volatile(
        "mma.sync.aligned.m16n8k16.row.col.f32.f16.f16.f32 "
        "{%0,%1,%2,%3}, {%4,%5,%6,%7}, {%8,%9}, {%0,%1,%2,%3};"
        : "+f"(c[0]), "+f"(c[1]), "+f"(c[2]), "+f"(c[3])
        : "r"(a[0]), "r"(a[1]), "r"(a[2]), "r"(a[3]), "r"(b0), "r"(b1));
}
__device__ __forceinline__ void cpasync16(uint32_t dst, const void* src) {
    asm volatile("cp.async.cg.shared.global [%0], [%1], 16;" :: "r"(dst), "l"(src) : "memory");
}

// ---------------- kernel A: ops->fp16 swizzled image + C/d0 precompute -------
__global__ void kA(const float* __restrict__ ops, const float* __restrict__ Wq,
                   const float* __restrict__ bq, const float* __restrict__ MK) {
    __shared__ float mk[128];
    __shared__ float part[128];
    const int b = blockIdx.x, tid = threadIdx.x;
    if (b < 512) {
        int idx = b * 256 + tid;                 // 16B-chunk id, 131072 total
        int m = idx >> 11, c = idx & 2047;
        int d = c >> 4, ch = c & 15;
        const float4* s = (const float4*)(ops + m * 16384 + d * 128 + ch * 8);
        float4 v0 = s[0], v1 = s[1];
        uint4 o;
        o.x = packh2(v0.x, v0.y); o.y = packh2(v0.z, v0.w);
        o.z = packh2(v1.x, v1.y); o.w = packh2(v1.z, v1.w);
        unsigned dst = (unsigned)m * 8192u + (unsigned)d * 64u
                     + (unsigned)((ch ^ (d & 7)) << 2);   // u32 units
        *(uint4*)(g_opsH + dst) = o;
    } else {
        const int m = b - 512;                   // 0..63
        if (tid < 128) mk[tid] = MK[m * 128 + tid];
        __syncthreads();
        const int d = tid & 127, half = tid >> 7;
        const int e0 = half * 64;
        float s = 0.f;
#pragma unroll 8
        for (int e = e0; e < e0 + 64; e++) s += Wq[e * 128 + d] * mk[e];
        if (half) part[d] = s;
        __syncthreads();
        const float inv = 0.08838834764831845f;
        if (!half) g_C[d * 64 + m] = (s + part[d]) * inv;
        if (tid == 0) {
            float s2 = 0.f;
#pragma unroll 8
            for (int e = 0; e < 128; e++) s2 += bq[e] * mk[e];
            g_d0[m] = s2 * inv;
        }
    }
}

// ---------------- kernel 2: fused attn + fp16 mma -----------------------------
// 148 CTAs x 512 thr (1/SM). CTA = ng*16 tokens (7 or 6 groups) x 128 dims.
// Warps 4 rows x 4 cols; row r owns groups {r, r+4}; col owns 32 dims.
// Group r (j=0): A hoisted to 32 persistent regs.  Group r+4 (j=1): per-slot
// ldsm from the RESIDENT x tile.  B: triple-buffered cp.async ring.
// SMEM map (141312 B):
//   AP   [0, 14336)        attn fp16x2 pairs (live whole kernel)
//   XS   [14336, 43008)    x tile fp16 swizzled (live whole kernel)
//   ring [43008, 141312)   3 x 32KB B buffers (mainloop)
//   init overlays inside ring: Cs = [43008, 75776), ls = [75776, 104896).
__global__ __launch_bounds__(512, 1) void k2_fused(const float* __restrict__ x,
                                                   float* __restrict__ out) {
    extern __shared__ __align__(16) unsigned char smraw[];
    const uint32_t SB = smem_u32(smraw);
    const uint32_t AP = SB;
    const uint32_t XS = SB + 14336u;
    const uint32_t BB = SB + 43008u;
    float* Cs = (float*)(smraw + 43008);          // 32KB (init phase)
    float* ls = (float*)(smraw + 75776);          // 29120 B (init phase)

    const int tid = threadIdx.x, l = tid & 31, w = tid >> 5;
    const int rowi = w >> 2, wd = (w & 3) * 32;
    const int cta = blockIdx.x;
    const int ng = (cta < 136) ? 7 : 6;
    const int t0 = (cta < 136) ? cta * 112 : 15232 + (cta - 136) * 96;
    const int ntok = ng * 16;

    // ---- stage x tile: fp32 -> fp16, XOR-swizzled [t][e] ----
    for (int idx = tid; idx < ntok * 16; idx += 512) {
        int row = idx >> 4, ch = idx & 15;
        const float4* sp = (const float4*)(x + (size_t)(t0 + row) * 128 + ch * 8);
        float4 v0 = sp[0], v1 = sp[1];
        uint4 o;
        o.x = packh2(v0.x, v0.y); o.y = packh2(v0.z, v0.w);
        o.z = packh2(v1.x, v1.y); o.w = packh2(v1.z, v1.w);
        asm volatile("st.shared.v4.b32 [%0], {%1,%2,%3,%4};"
                     :: "r"(XS + (unsigned)(row * 256) + (unsigned)((ch ^ (row & 7)) << 4)),
                        "r"(o.x), "r"(o.y), "r"(o.z), "r"(o.w) : "memory");
    }
    // ---- stage C (32 KB) ----
    for (int idx = tid; idx < 2048; idx += 512)
        ((float4*)Cs)[idx] = ((const float4*)g_C)[idx];
    __syncthreads();

    // ---- logits: fp32 (x from gmem, L2-hot) ----
    {
        const int t = tid >> 2, mg = tid & 3;
        if (t < ntok) {
            float acc[16];
#pragma unroll
            for (int j = 0; j < 16; j++) acc[j] = g_d0[mg * 16 + j];
            const float4* xp = (const float4*)(x + (size_t)(t0 + t) * 128);
#pragma unroll 4
            for (int d4 = 0; d4 < 32; d4++) {
                float4 xv4 = xp[d4];
                const float* cb = Cs + (d4 * 4) * 64 + mg * 16;
#pragma unroll
                for (int q = 0; q < 4; q++) {
                    float xv = (q == 0) ? xv4.x : (q == 1) ? xv4.y : (q == 2) ? xv4.z : xv4.w;
                    const float4* c4 = (const float4*)(cb + q * 64);
#pragma unroll
                    for (int j4 = 0; j4 < 4; j4++) {
                        float4 cc = c4[j4];
                        acc[j4*4+0] = fmaf(xv, cc.x, acc[j4*4+0]);
                        acc[j4*4+1] = fmaf(xv, cc.y, acc[j4*4+1]);
                        acc[j4*4+2] = fmaf(xv, cc.z, acc[j4*4+2]);
                        acc[j4*4+3] = fmaf(xv, cc.w, acc[j4*4+3]);
                    }
                }
            }
#pragma unroll
            for (int j = 0; j < 16; j++) ls[t * 65 + mg * 16 + j] = acc[j];
        }
    }
    __syncthreads();
    // ---- softmax per token ----
    if (tid < ntok) {
        float mx = -1e30f;
#pragma unroll 8
        for (int m = 0; m < 64; m++) mx = fmaxf(mx, ls[tid * 65 + m]);
        float s = 0.f;
#pragma unroll 8
        for (int m = 0; m < 64; m++) { float e = __expf(ls[tid*65+m]-mx); ls[tid*65+m] = e; s += e; }
        float iv = 1.f / s;
#pragma unroll 8
        for (int m = 0; m < 64; m++) ls[tid * 65 + m] *= iv;
    }
    __syncthreads();
    // ---- pack attn pairs (t, t+8) fp16x2 into AP [m][56] ----
    for (int idx = tid; idx < 64 * 56; idx += 512) {
        int m = idx / 56, p = idx - m * 56;
        int g = p >> 3;
        if (g < ng) {
            int tl = g * 16 + (p & 7);
            unsigned u = packh2(ls[tl * 65 + m], ls[(tl + 8) * 65 + m]);
            asm volatile("st.shared.b32 [%0], %1;" :: "r"(AP + (unsigned)idx * 4), "r"(u) : "memory");
        }
    }
    // ---- hoist group j=0 (g = rowi, always valid) A fragments to regs ----
    unsigned Areg[8][4];
    {
        const int r_off = l & 15;
        const int row = rowi * 16 + r_off;
#pragma unroll
        for (int ks = 0; ks < 8; ks++) {
            int chA = ks * 2 + (l >> 4);
            uint32_t addr = XS + row * 256 + ((chA ^ (r_off & 7)) << 4);
            ldsm4(Areg[ks], addr);
        }
    }
    __syncthreads();   // Cs/ls dead -> ring usable (XS stays resident)

    // ---- prologue: B(0), B(1) into ring ----
#pragma unroll
    for (int i = 0; i < 4; i++) {
        int idx = tid + i * 512;
        cpasync16(BB + idx * 16, (const char*)g_opsH + idx * 16);
    }
    asm volatile("cp.async.commit_group;" ::: "memory");
#pragma unroll
    for (int i = 0; i < 4; i++) {
        int idx = tid + i * 512;
        cpasync16(BB + 32768u + idx * 16, (const char*)g_opsH + 32768 + idx * 16);
    }
    asm volatile("cp.async.commit_group;" ::: "memory");

    float acc[2][4][4] = {};
    const int g1 = rowi + 4;            // second group (may be inactive)
    const bool has1 = (g1 < ng);

    for (int m = 0; m < 64; m++) {
        if (m == 63) { asm volatile("cp.async.wait_group 0;" ::: "memory"); }
        else         { asm volatile("cp.async.wait_group 1;" ::: "memory"); }
        __syncthreads();
        if (m + 2 < 64) {
            const char* src = (const char*)g_opsH + (size_t)(m + 2) * 32768;
            uint32_t dst = BB + (unsigned)((m + 2) % 3) * 32768u;
#pragma unroll
            for (int i = 0; i < 4; i++) {
                int idx = tid + i * 512;
                cpasync16(dst + idx * 16, src + idx * 16);
            }
            asm volatile("cp.async.commit_group;" ::: "memory");
        }

        // attn splats for this slot
        unsigned lo2[2], hi2[2];
        {
            unsigned pu;
            asm volatile("ld.shared.b32 %0, [%1];"
                         : "=r"(pu) : "r"(AP + (unsigned)(m * 56 + rowi * 8 + (l >> 2)) * 4));
            asm("prmt.b32 %0, %1, %1, 0x1010;" : "=r"(lo2[0]) : "r"(pu));
            asm("prmt.b32 %0, %1, %1, 0x3232;" : "=r"(hi2[0]) : "r"(pu));
        }
        if (has1) {
            unsigned pu;
            asm volatile("ld.shared.b32 %0, [%1];"
                         : "=r"(pu) : "r"(AP + (unsigned)(m * 56 + g1 * 8 + (l >> 2)) * 4));
            asm("prmt.b32 %0, %1, %1, 0x1010;" : "=r"(lo2[1]) : "r"(pu));
            asm("prmt.b32 %0, %1, %1, 0x3232;" : "=r"(hi2[1]) : "r"(pu));
        }

        const uint32_t Bb = BB + (unsigned)(m % 3) * 32768u;
#pragma unroll
        for (int ks = 0; ks < 8; ks++) {
            const int c0 = ks * 2;
            unsigned bf[2][4];
            {
                int n_off = ((l >> 4) << 3) + (l & 7);
                int chB = c0 + ((l >> 3) & 1);
#pragma unroll
                for (int np = 0; np < 2; np++) {
                    int row = wd + np * 16 + n_off;
                    uint32_t addr = Bb + row * 256 + ((chB ^ (row & 7)) << 4);
                    ldsm4(bf[np], addr);
                }
            }
            // group 0: hoisted A
            {
                unsigned t[4];
                t[0] = hmul2(Areg[ks][0], lo2[0]);
                t[1] = hmul2(Areg[ks][1], hi2[0]);
                t[2] = hmul2(Areg[ks][2], lo2[0]);
                t[3] = hmul2(Areg[ks][3], hi2[0]);
#pragma unroll
                for (int nt = 0; nt < 4; nt++)
                    mma16816(acc[0][nt], t, bf[nt >> 1][(nt & 1) * 2],
                             bf[nt >> 1][(nt & 1) * 2 + 1]);
            }
            // group 1: per-slot ldsm from resident x tile
            if (has1) {
                const int r_off = l & 15;
                int chA = c0 + (l >> 4);
                int row = g1 * 16 + r_off;
                uint32_t addr = XS + row * 256 + ((chA ^ (r_off & 7)) << 4);
                unsigned a[4];
                ldsm4(a, addr);
                unsigned t[4];
                t[0] = hmul2(a[0], lo2[1]);
                t[1] = hmul2(a[1], hi2[1]);
                t[2] = hmul2(a[2], lo2[1]);
                t[3] = hmul2(a[3], hi2[1]);
#pragma unroll
                for (int nt = 0; nt < 4; nt++)
                    mma16816(acc[1][nt], t, bf[nt >> 1][(nt & 1) * 2],
                             bf[nt >> 1][(nt & 1) * 2 + 1]);
            }
        }
    }

    // ---- writeback ----
#pragma unroll
    for (int j = 0; j < 2; j++) {
        int g = rowi + 4 * j;
        if (j == 0 || has1) {
            int row = t0 + g * 16 + (l >> 2);
#pragma unroll
            for (int nt = 0; nt < 4; nt++) {
                int col = wd + nt * 8 + (l & 3) * 2;
                *(float2*)(out + (size_t)row * 128 + col) =
                    make_float2(acc[j][nt][0], acc[j][nt][1]);
                *(float2*)(out + (size_t)(row + 8) * 128 + col) =
                    make_float2(acc[j][nt][2], acc[j][nt][3]);
            }
        }
    }
}

// ---------------------------------------------------------------------------
extern "C" void kernel_launch(void* const* d_in, const int* in_sizes, int n_in,
                              void* d_out, int out_size) {
    const float* x   = (const float*)d_in[0];   // [4,4096,128]
    const float* MK  = (const float*)d_in[1];   // [64,128]
    const float* ops = (const float*)d_in[2];   // [64,128,128]
    const float* Wq  = (const float*)d_in[3];   // [128,128]
    const float* bq  = (const float*)d_in[4];   // [128]
    float* out = (float*)d_out;

    const int smem2 = 141312;
    cudaFuncSetAttribute(k2_fused, cudaFuncAttributeMaxDynamicSharedMemorySize, smem2);

    kA<<<576, 256>>>(ops, Wq, bq, MK);
    k2_fused<<<148, 512, smem2>>>(x, out);
}

// round 14
// speedup vs baseline: 1.1361x; 1.0583x over previous
#include <cuda_runtime.h>
#include <cuda_fp16.h>
#include <cstdint>

#define TOKENS 16384
#define DIMS   128
#define SLOTS  64

// ---------------- device globals ---------------------------------------------
__device__ __align__(16) float g_C[DIMS * SLOTS];        // C[d][m], pre-scaled
__device__ __align__(16) float g_d0[SLOTS];               // bias, pre-scaled
__device__ __align__(16) unsigned g_opsH[SLOTS * DIMS * 64]; // fp16 ops, swizzled (2MB)

// ---------------- helpers ----------------------------------------------------
__device__ __forceinline__ uint32_t smem_u32(const void* p) {
    uint32_t a;
    asm("{ .reg .u64 t; cvta.to.shared.u64 t, %1; cvt.u32.u64 %0, t; }" : "=r"(a) : "l"(p));
    return a;
}
__device__ __forceinline__ unsigned packh2(float lo, float hi) {
    unsigned u;
    asm("{ .reg .f16 l, h; cvt.rn.f16.f32 l, %1; cvt.rn.f16.f32 h, %2; mov.b32 %0, {l, h}; }"
        : "=r"(u) : "f"(lo), "f"(hi));
    return u;
}
__device__ __forceinline__ unsigned hmul2(unsigned a, unsigned b) {
    unsigned r; asm("mul.rn.f16x2 %0, %1, %2;" : "=r"(r) : "r"(a), "r"(b)); return r;
}
__device__ __forceinline__ void ldsm4(unsigned* r, uint32_t addr) {
    asm volatile("ldmatrix.sync.aligned.m8n8.x4.shared.b16 {%0,%1,%2,%3}, [%4];"
                 : "=r"(r[0]), "=r"(r[1]), "=r"(r[2]), "=r"(r[3]) : "r"(addr));
}
__device__ __forceinline__ void mma16816(float* c, const unsigned* a, unsigned b0, unsigned b1) {
    asm volatile(
        "mma.sync.aligned.m16n8k16.row.col.f32.f16.f16.f32 "
        "{%0,%1,%2,%3}, {%4,%5,%6,%7}, {%8,%9}, {%0,%1,%2,%3};"
        : "+f"(c[0]), "+f"(c[1]), "+f"(c[2]), "+f"(c[3])
        : "r"(a[0]), "r"(a[1]), "r"(a[2]), "r"(a[3]), "r"(b0), "r"(b1));
}
__device__ __forceinline__ void cpasync16(uint32_t dst, const void* src) {
    asm volatile("cp.async.cg.shared.global [%0], [%1], 16;" :: "r"(dst), "l"(src) : "memory");
}

// ---------------- kernel A: ops->fp16 swizzled image + C/d0 precompute -------
__global__ void kA(const float* __restrict__ ops, const float* __restrict__ Wq,
                   const float* __restrict__ bq, const float* __restrict__ MK) {
    __shared__ float mk[128];
    __shared__ float part[128];
    const int b = blockIdx.x, tid = threadIdx.x;
    if (b < 512) {
        int idx = b * 256 + tid;                 // 16B-chunk id, 131072 total
        int m = idx >> 11, c = idx & 2047;
        int d = c >> 4, ch = c & 15;
        const float4* s = (const float4*)(ops + m * 16384 + d * 128 + ch * 8);
        float4 v0 = s[0], v1 = s[1];
        uint4 o;
        o.x = packh2(v0.x, v0.y); o.y = packh2(v0.z, v0.w);
        o.z = packh2(v1.x, v1.y); o.w = packh2(v1.z, v1.w);
        unsigned dst = (unsigned)m * 8192u + (unsigned)d * 64u
                     + (unsigned)((ch ^ (d & 7)) << 2);   // u32 units
        *(uint4*)(g_opsH + dst) = o;
    } else {
        const int m = b - 512;                   // 0..63
        if (tid < 128) mk[tid] = MK[m * 128 + tid];
        __syncthreads();
        const int d = tid & 127, half = tid >> 7;
        const int e0 = half * 64;
        float s = 0.f;
#pragma unroll 8
        for (int e = e0; e < e0 + 64; e++) s += Wq[e * 128 + d] * mk[e];
        if (half) part[d] = s;
        __syncthreads();
        const float inv = 0.08838834764831845f;
        if (!half) g_C[d * 64 + m] = (s + part[d]) * inv;
        if (tid == 0) {
            float s2 = 0.f;
#pragma unroll 8
            for (int e = 0; e < 128; e++) s2 += bq[e] * mk[e];
            g_d0[m] = s2 * inv;
        }
    }
}

// ---------------- kernel 2: fused attn + fp16 mma -----------------------------
// 148 CTAs x 512 thr (1/SM). CTA = ng*16 tokens (7 or 6 groups) x 128 dims.
// Warps 4 rows x 4 cols; row r owns groups {r, r+4}; col owns 32 dims.
// Group r: A hoisted to 32 persistent regs.  Group r+4: per-slot ldsm from
// the RESIDENT x tile.  B: 2 x 64KB double buffer (2 slots per buffer).
// Race-free order per iteration: wait_group 0 -> syncthreads -> issue
// prefetch into other buffer -> compute pair.  Buffer 0 preloaded before
// the attn prologue (overlaps ~13us of FFMA/softmax).
// SMEM map (174080 B):
//   AP   [0, 14336)          attn fp16x2 pairs (live whole kernel)
//   XS   [14336, 43008)      x tile fp16 swizzled (live whole kernel)
//   ring [43008, 174080)     2 x 64KB B buffers
//   init overlays INSIDE BUFFER 1 only: Cs=[108544,141312), ls=[141312,170432).
__global__ __launch_bounds__(512, 1) void k2_fused(const float* __restrict__ x,
                                                   float* __restrict__ out) {
    extern __shared__ __align__(16) unsigned char smraw[];
    const uint32_t SB = smem_u32(smraw);
    const uint32_t AP = SB;
    const uint32_t XS = SB + 14336u;
    const uint32_t BB = SB + 43008u;
    float* Cs = (float*)(smraw + 108544);         // inside buffer 1 (init phase)
    float* ls = (float*)(smraw + 141312);         // inside buffer 1 (init phase)

    const int tid = threadIdx.x, l = tid & 31, w = tid >> 5;
    const int rowi = w >> 2, wd = (w & 3) * 32;
    const int cta = blockIdx.x;
    const int ng = (cta < 136) ? 7 : 6;
    const int t0 = (cta < 136) ? cta * 112 : 15232 + (cta - 136) * 96;
    const int ntok = ng * 16;

    // ---- kick off B(slots 0,1) into buffer 0 FIRST (overlaps prologue) ----
#pragma unroll
    for (int i = 0; i < 8; i++) {
        int idx = tid + i * 512;
        cpasync16(BB + idx * 16, (const char*)g_opsH + idx * 16);
    }
    asm volatile("cp.async.commit_group;" ::: "memory");

    // ---- stage x tile: fp32 -> fp16, XOR-swizzled [t][e] ----
    for (int idx = tid; idx < ntok * 16; idx += 512) {
        int row = idx >> 4, ch = idx & 15;
        const float4* sp = (const float4*)(x + (size_t)(t0 + row) * 128 + ch * 8);
        float4 v0 = sp[0], v1 = sp[1];
        uint4 o;
        o.x = packh2(v0.x, v0.y); o.y = packh2(v0.z, v0.w);
        o.z = packh2(v1.x, v1.y); o.w = packh2(v1.z, v1.w);
        asm volatile("st.shared.v4.b32 [%0], {%1,%2,%3,%4};"
                     :: "r"(XS + (unsigned)(row * 256) + (unsigned)((ch ^ (row & 7)) << 4)),
                        "r"(o.x), "r"(o.y), "r"(o.z), "r"(o.w) : "memory");
    }
    // ---- stage C (32 KB, inside buffer 1) ----
    for (int idx = tid; idx < 2048; idx += 512)
        ((float4*)Cs)[idx] = ((const float4*)g_C)[idx];
    __syncthreads();

    // ---- logits: fp32 (x from gmem, L2-hot) ----
    {
        const int t = tid >> 2, mg = tid & 3;
        if (t < ntok) {
            float acc[16];
#pragma unroll
            for (int j = 0; j < 16; j++) acc[j] = g_d0[mg * 16 + j];
            const float4* xp = (const float4*)(x + (size_t)(t0 + t) * 128);
#pragma unroll 4
            for (int d4 = 0; d4 < 32; d4++) {
                float4 xv4 = xp[d4];
                const float* cb = Cs + (d4 * 4) * 64 + mg * 16;
#pragma unroll
                for (int q = 0; q < 4; q++) {
                    float xv = (q == 0) ? xv4.x : (q == 1) ? xv4.y : (q == 2) ? xv4.z : xv4.w;
                    const float4* c4 = (const float4*)(cb + q * 64);
#pragma unroll
                    for (int j4 = 0; j4 < 4; j4++) {
                        float4 cc = c4[j4];
                        acc[j4*4+0] = fmaf(xv, cc.x, acc[j4*4+0]);
                        acc[j4*4+1] = fmaf(xv, cc.y, acc[j4*4+1]);
                        acc[j4*4+2] = fmaf(xv, cc.z, acc[j4*4+2]);
                        acc[j4*4+3] = fmaf(xv, cc.w, acc[j4*4+3]);
                    }
                }
            }
#pragma unroll
            for (int j = 0; j < 16; j++) ls[t * 65 + mg * 16 + j] = acc[j];
        }
    }
    __syncthreads();
    // ---- softmax per token ----
    if (tid < ntok) {
        float mx = -1e30f;
#pragma unroll 8
        for (int m = 0; m < 64; m++) mx = fmaxf(mx, ls[tid * 65 + m]);
        float s = 0.f;
#pragma unroll 8
        for (int m = 0; m < 64; m++) { float e = __expf(ls[tid*65+m]-mx); ls[tid*65+m] = e; s += e; }
        float iv = 1.f / s;
#pragma unroll 8
        for (int m = 0; m < 64; m++) ls[tid * 65 + m] *= iv;
    }
    __syncthreads();
    // ---- pack attn pairs (t, t+8) fp16x2 into AP [m][56] ----
    for (int idx = tid; idx < 64 * 56; idx += 512) {
        int m = idx / 56, p = idx - m * 56;
        int g = p >> 3;
        if (g < ng) {
            int tl = g * 16 + (p & 7);
            unsigned u = packh2(ls[tl * 65 + m], ls[(tl + 8) * 65 + m]);
            asm volatile("st.shared.b32 [%0], %1;" :: "r"(AP + (unsigned)idx * 4), "r"(u) : "memory");
        }
    }
    // ---- hoist group j=0 (g = rowi) A fragments to regs ----
    unsigned Areg[8][4];
    {
        const int r_off = l & 15;
        const int row = rowi * 16 + r_off;
#pragma unroll
        for (int ks = 0; ks < 8; ks++) {
            int chA = ks * 2 + (l >> 4);
            uint32_t addr = XS + row * 256 + ((chA ^ (r_off & 7)) << 4);
            ldsm4(Areg[ks], addr);
        }
    }
    __syncthreads();   // Cs/ls dead -> buffer 1 usable

    float acc[2][4][4] = {};
    const int g1 = rowi + 4;
    const bool has1 = (g1 < ng);

    for (int it = 0; it < 32; it++) {
        const int m0 = it * 2;
        // current pair's buffer fully loaded; previous compute finished by all
        asm volatile("cp.async.wait_group 0;" ::: "memory");
        __syncthreads();
        // now safe to overwrite the OTHER buffer (everyone done reading it)
        if (it < 31) {
            const char* src = (const char*)g_opsH + (size_t)(m0 + 2) * 32768;
            uint32_t dst = BB + (unsigned)((it + 1) & 1) * 65536u;
#pragma unroll
            for (int i = 0; i < 8; i++) {
                int idx = tid + i * 512;
                cpasync16(dst + idx * 16, src + idx * 16);
            }
            asm volatile("cp.async.commit_group;" ::: "memory");
        }

        const uint32_t BufB = BB + (unsigned)(it & 1) * 65536u;
#pragma unroll
        for (int sm = 0; sm < 2; sm++) {
            const int m = m0 + sm;
            // attn splats for this slot
            unsigned lo2[2], hi2[2];
            {
                unsigned pu;
                asm volatile("ld.shared.b32 %0, [%1];"
                             : "=r"(pu) : "r"(AP + (unsigned)(m * 56 + rowi * 8 + (l >> 2)) * 4));
                asm("prmt.b32 %0, %1, %1, 0x1010;" : "=r"(lo2[0]) : "r"(pu));
                asm("prmt.b32 %0, %1, %1, 0x3232;" : "=r"(hi2[0]) : "r"(pu));
            }
            if (has1) {
                unsigned pu;
                asm volatile("ld.shared.b32 %0, [%1];"
                             : "=r"(pu) : "r"(AP + (unsigned)(m * 56 + g1 * 8 + (l >> 2)) * 4));
                asm("prmt.b32 %0, %1, %1, 0x1010;" : "=r"(lo2[1]) : "r"(pu));
                asm("prmt.b32 %0, %1, %1, 0x3232;" : "=r"(hi2[1]) : "r"(pu));
            }

            const uint32_t Bb = BufB + (unsigned)sm * 32768u;
#pragma unroll
            for (int ks = 0; ks < 8; ks++) {
                const int c0 = ks * 2;
                unsigned bf[2][4];
                {
                    int n_off = ((l >> 4) << 3) + (l & 7);
                    int chB = c0 + ((l >> 3) & 1);
#pragma unroll
                    for (int np = 0; np < 2; np++) {
                        int row = wd + np * 16 + n_off;
                        uint32_t addr = Bb + row * 256 + ((chB ^ (row & 7)) << 4);
                        ldsm4(bf[np], addr);
                    }
                }
                // group 0: hoisted A
                {
                    unsigned t[4];
                    t[0] = hmul2(Areg[ks][0], lo2[0]);
                    t[1] = hmul2(Areg[ks][1], hi2[0]);
                    t[2] = hmul2(Areg[ks][2], lo2[0]);
                    t[3] = hmul2(Areg[ks][3], hi2[0]);
#pragma unroll
                    for (int nt = 0; nt < 4; nt++)
                        mma16816(acc[0][nt], t, bf[nt >> 1][(nt & 1) * 2],
                                 bf[nt >> 1][(nt & 1) * 2 + 1]);
                }
                // group 1: per-slot ldsm from resident x tile
                if (has1) {
                    const int r_off = l & 15;
                    int chA = c0 + (l >> 4);
                    int row = g1 * 16 + r_off;
                    uint32_t addr = XS + row * 256 + ((chA ^ (r_off & 7)) << 4);
                    unsigned a[4];
                    ldsm4(a, addr);
                    unsigned t[4];
                    t[0] = hmul2(a[0], lo2[1]);
                    t[1] = hmul2(a[1], hi2[1]);
                    t[2] = hmul2(a[2], lo2[1]);
                    t[3] = hmul2(a[3], hi2[1]);
#pragma unroll
                    for (int nt = 0; nt < 4; nt++)
                        mma16816(acc[1][nt], t, bf[nt >> 1][(nt & 1) * 2],
                                 bf[nt >> 1][(nt & 1) * 2 + 1]);
                }
            }
        }
    }

    // ---- writeback ----
#pragma unroll
    for (int j = 0; j < 2; j++) {
        int g = rowi + 4 * j;
        if (j == 0 || has1) {
            int row = t0 + g * 16 + (l >> 2);
#pragma unroll
            for (int nt = 0; nt < 4; nt++) {
                int col = wd + nt * 8 + (l & 3) * 2;
                *(float2*)(out + (size_t)row * 128 + col) =
                    make_float2(acc[j][nt][0], acc[j][nt][1]);
                *(float2*)(out + (size_t)(row + 8) * 128 + col) =
                    make_float2(acc[j][nt][2], acc[j][nt][3]);
            }
        }
    }
}

// ---------------------------------------------------------------------------
extern "C" void kernel_launch(void* const* d_in, const int* in_sizes, int n_in,
                              void* d_out, int out_size) {
    const float* x   = (const float*)d_in[0];   // [4,4096,128]
    const float* MK  = (const float*)d_in[1];   // [64,128]
    const float* ops = (const float*)d_in[2];   // [64,128,128]
    const float* Wq  = (const float*)d_in[3];   // [128,128]
    const float* bq  = (const float*)d_in[4];   // [128]
    float* out = (float*)d_out;

    const int smem2 = 174080;
    cudaFuncSetAttribute(k2_fused, cudaFuncAttributeMaxDynamicSharedMemorySize, smem2);

    kA<<<576, 256>>>(ops, Wq, bq, MK);
    k2_fused<<<148, 512, smem2>>>(x, out);
}

// round 15
// speedup vs baseline: 1.1630x; 1.0237x over previous
#include <cuda_runtime.h>
#include <cuda_fp16.h>
#include <cstdint>

#define TOKENS 16384
#define DIMS   128
#define SLOTS  64

// ---------------- device globals ---------------------------------------------
__device__ __align__(16) float g_C[DIMS * SLOTS];        // C[d][m], pre-scaled
__device__ __align__(16) float g_d0[SLOTS];               // bias, pre-scaled
__device__ __align__(16) unsigned g_opsH[SLOTS * DIMS * 64]; // fp16 ops, swizzled (2MB)

// ---------------- helpers ----------------------------------------------------
__device__ __forceinline__ uint32_t smem_u32(const void* p) {
    uint32_t a;
    asm("{ .reg .u64 t; cvta.to.shared.u64 t, %1; cvt.u32.u64 %0, t; }" : "=r"(a) : "l"(p));
    return a;
}
__device__ __forceinline__ unsigned packh2(float lo, float hi) {
    unsigned u;
    asm("{ .reg .f16 l, h; cvt.rn.f16.f32 l, %1; cvt.rn.f16.f32 h, %2; mov.b32 %0, {l, h}; }"
        : "=r"(u) : "f"(lo), "f"(hi));
    return u;
}
__device__ __forceinline__ unsigned hmul2(unsigned a, unsigned b) {
    unsigned r; asm("mul.rn.f16x2 %0, %1, %2;" : "=r"(r) : "r"(a), "r"(b)); return r;
}
__device__ __forceinline__ void ldsm4(unsigned* r, uint32_t addr) {
    asm volatile("ldmatrix.sync.aligned.m8n8.x4.shared.b16 {%0,%1,%2,%3}, [%4];"
                 : "=r"(r[0]), "=r"(r[1]), "=r"(r[2]), "=r"(r[3]) : "r"(addr));
}
__device__ __forceinline__ void mma16816(float* c, const unsigned* a, unsigned b0, unsigned b1) {
    asm volatile(
        "mma.sync.aligned.m16n8k16.row.col.f32.f16.f16.f32 "
        "{%0,%1,%2,%3}, {%4,%5,%6,%7}, {%8,%9}, {%0,%1,%2,%3};"
        : "+f"(c[0]), "+f"(c[1]), "+f"(c[2]), "+f"(c[3])
        : "r"(a[0]), "r"(a[1]), "r"(a[2]), "r"(a[3]), "r"(b0), "r"(b1));
}
__device__ __forceinline__ void cpasync16(uint32_t dst, const void* src) {
    asm volatile("cp.async.cg.shared.global [%0], [%1], 16;" :: "r"(dst), "l"(src) : "memory");
}

// ---------------- kernel A: ops->fp16 swizzled image + C/d0 precompute -------
__global__ void kA(const float* __restrict__ ops, const float* __restrict__ Wq,
                   const float* __restrict__ bq, const float* __restrict__ MK) {
    __shared__ float mk[128];
    __shared__ float part[128];
    const int b = blockIdx.x, tid = threadIdx.x;
    if (b < 512) {
        int idx = b * 256 + tid;                 // 16B-chunk id, 131072 total
        int m = idx >> 11, c = idx & 2047;
        int d = c >> 4, ch = c & 15;
        const float4* s = (const float4*)(ops + m * 16384 + d * 128 + ch * 8);
        float4 v0 = s[0], v1 = s[1];
        uint4 o;
        o.x = packh2(v0.x, v0.y); o.y = packh2(v0.z, v0.w);
        o.z = packh2(v1.x, v1.y); o.w = packh2(v1.z, v1.w);
        unsigned dst = (unsigned)m * 8192u + (unsigned)d * 64u
                     + (unsigned)((ch ^ (d & 7)) << 2);   // u32 units
        *(uint4*)(g_opsH + dst) = o;
    } else {
        const int m = b - 512;                   // 0..63
        if (tid < 128) mk[tid] = MK[m * 128 + tid];
        __syncthreads();
        const int d = tid & 127, half = tid >> 7;
        const int e0 = half * 64;
        float s = 0.f;
#pragma unroll 8
        for (int e = e0; e < e0 + 64; e++) s += Wq[e * 128 + d] * mk[e];
        if (half) part[d] = s;
        __syncthreads();
        const float inv = 0.08838834764831845f;
        if (!half) g_C[d * 64 + m] = (s + part[d]) * inv;
        if (tid == 0) {
            float s2 = 0.f;
#pragma unroll 8
            for (int e = 0; e < 128; e++) s2 += bq[e] * mk[e];
            g_d0[m] = s2 * inv;
        }
    }
}

// ---------------- kernel 2: fused attn + fp16 mma, column-decoupled B rings ---
// 148 CTAs x 512 thr (1/SM). CTA = ng*16 tokens (7 or 6 groups) x 128 dims.
// Warps 4 rows x 4 cols; row r owns groups {r, r+4}; col c owns dims [32c,32c+32).
// Each COLUMN owns a private B ring (its 4 warps load only their 8KB strip per
// slot) gated by a per-column named barrier (bar.sync c+1, 128) -> no CTA-wide
// sync in the mainloop; columns free-run.
// SMEM map (174080 B):
//   AP   [0, 14336)        attn fp16x2 pairs (live whole kernel)
//   XS   [14336, 43008)    x tile fp16 swizzled (live whole kernel)
//   ring [43008, 174080)   layout [buf(2)][col(4)][slot(2)][8KB]
//   init overlays in BUF 1 only: Cs=[108544,141312), ls=[141312,170432).
__global__ __launch_bounds__(512, 1) void k2_fused(const float* __restrict__ x,
                                                   float* __restrict__ out) {
    extern __shared__ __align__(16) unsigned char smraw[];
    const uint32_t SB = smem_u32(smraw);
    const uint32_t AP = SB;
    const uint32_t XS = SB + 14336u;
    const uint32_t BB = SB + 43008u;
    float* Cs = (float*)(smraw + 108544);         // inside buf 1 (init phase)
    float* ls = (float*)(smraw + 141312);         // inside buf 1 (init phase)

    const int tid = threadIdx.x, l = tid & 31, w = tid >> 5;
    const int rowi = w >> 2, col = w & 3, wd = col * 32;
    const unsigned cid = (unsigned)(rowi * 32 + l);   // 0..127 within column
    const uint32_t colB = BB + (unsigned)col * 16384u;
    const int cta = blockIdx.x;
    const int ng = (cta < 136) ? 7 : 6;
    const int t0 = (cta < 136) ? cta * 112 : 15232 + (cta - 136) * 96;
    const int ntok = ng * 16;

    // ---- preload pair 0 (column strip) into buf 0 — overlaps prologue ----
#pragma unroll
    for (int i = 0; i < 8; i++) {
        int ch = i * 128 + (int)cid;          // 0..1023
        int sm = ch >> 9, r = (ch >> 4) & 31, cc = ch & 15;
        const char* src = (const char*)g_opsH + (size_t)sm * 32768 + (wd + r) * 256 + cc * 16;
        cpasync16(colB + (unsigned)(sm * 8192 + r * 256 + cc * 16), src);
    }
    asm volatile("cp.async.commit_group;" ::: "memory");

    // ---- stage x tile: fp32 -> fp16, XOR-swizzled [t][e] ----
    for (int idx = tid; idx < ntok * 16; idx += 512) {
        int row = idx >> 4, ch = idx & 15;
        const float4* sp = (const float4*)(x + (size_t)(t0 + row) * 128 + ch * 8);
        float4 v0 = sp[0], v1 = sp[1];
        uint4 o;
        o.x = packh2(v0.x, v0.y); o.y = packh2(v0.z, v0.w);
        o.z = packh2(v1.x, v1.y); o.w = packh2(v1.z, v1.w);
        asm volatile("st.shared.v4.b32 [%0], {%1,%2,%3,%4};"
                     :: "r"(XS + (unsigned)(row * 256) + (unsigned)((ch ^ (row & 7)) << 4)),
                        "r"(o.x), "r"(o.y), "r"(o.z), "r"(o.w) : "memory");
    }
    // ---- stage C (32 KB, inside buf 1) ----
    for (int idx = tid; idx < 2048; idx += 512)
        ((float4*)Cs)[idx] = ((const float4*)g_C)[idx];
    __syncthreads();

    // ---- logits: fp32 (x from gmem, L2-hot) ----
    {
        const int t = tid >> 2, mg = tid & 3;
        if (t < ntok) {
            float acc[16];
#pragma unroll
            for (int j = 0; j < 16; j++) acc[j] = g_d0[mg * 16 + j];
            const float4* xp = (const float4*)(x + (size_t)(t0 + t) * 128);
#pragma unroll 4
            for (int d4 = 0; d4 < 32; d4++) {
                float4 xv4 = xp[d4];
                const float* cb = Cs + (d4 * 4) * 64 + mg * 16;
#pragma unroll
                for (int q = 0; q < 4; q++) {
                    float xv = (q == 0) ? xv4.x : (q == 1) ? xv4.y : (q == 2) ? xv4.z : xv4.w;
                    const float4* c4 = (const float4*)(cb + q * 64);
#pragma unroll
                    for (int j4 = 0; j4 < 4; j4++) {
                        float4 cc = c4[j4];
                        acc[j4*4+0] = fmaf(xv, cc.x, acc[j4*4+0]);
                        acc[j4*4+1] = fmaf(xv, cc.y, acc[j4*4+1]);
                        acc[j4*4+2] = fmaf(xv, cc.z, acc[j4*4+2]);
                        acc[j4*4+3] = fmaf(xv, cc.w, acc[j4*4+3]);
                    }
                }
            }
#pragma unroll
            for (int j = 0; j < 16; j++) ls[t * 65 + mg * 16 + j] = acc[j];
        }
    }
    __syncthreads();
    // ---- softmax per token ----
    if (tid < ntok) {
        float mx = -1e30f;
#pragma unroll 8
        for (int m = 0; m < 64; m++) mx = fmaxf(mx, ls[tid * 65 + m]);
        float s = 0.f;
#pragma unroll 8
        for (int m = 0; m < 64; m++) { float e = __expf(ls[tid*65+m]-mx); ls[tid*65+m] = e; s += e; }
        float iv = 1.f / s;
#pragma unroll 8
        for (int m = 0; m < 64; m++) ls[tid * 65 + m] *= iv;
    }
    __syncthreads();
    // ---- pack attn pairs (t, t+8) fp16x2 into AP [m][56] ----
    for (int idx = tid; idx < 64 * 56; idx += 512) {
        int m = idx / 56, p = idx - m * 56;
        int g = p >> 3;
        if (g < ng) {
            int tl = g * 16 + (p & 7);
            unsigned u = packh2(ls[tl * 65 + m], ls[(tl + 8) * 65 + m]);
            asm volatile("st.shared.b32 [%0], %1;" :: "r"(AP + (unsigned)idx * 4), "r"(u) : "memory");
        }
    }
    // ---- hoist group j=0 (g = rowi) A fragments to regs ----
    unsigned Areg[8][4];
    {
        const int r_off = l & 15;
        const int row = rowi * 16 + r_off;
#pragma unroll
        for (int ks = 0; ks < 8; ks++) {
            int chA = ks * 2 + (l >> 4);
            uint32_t addr = XS + row * 256 + ((chA ^ (r_off & 7)) << 4);
            ldsm4(Areg[ks], addr);
        }
    }
    __syncthreads();   // Cs/ls dead -> buf 1 usable; prologue done for ALL cols

    float acc[2][4][4] = {};
    const int g1 = rowi + 4;
    const bool has1 = (g1 < ng);
    const unsigned barid = (unsigned)(col + 1);

    for (int it = 0; it < 32; it++) {
        const int m0 = it * 2;
        // this column's current-pair loads complete for THIS warp...
        asm volatile("cp.async.wait_group 0;" ::: "memory");
        // ...and for all 4 warps of the column (named barrier, 128 threads)
        asm volatile("bar.sync %0, 128;" :: "r"(barid) : "memory");
        // safe to overwrite the other buffer's column strip now
        if (it < 31) {
            const unsigned buf = (unsigned)((it + 1) & 1);
            const size_t sbase = (size_t)(m0 + 2) * 32768;
#pragma unroll
            for (int i = 0; i < 8; i++) {
                int ch = i * 128 + (int)cid;
                int sm = ch >> 9, r = (ch >> 4) & 31, cc = ch & 15;
                const char* src = (const char*)g_opsH + sbase + (size_t)sm * 32768
                                + (wd + r) * 256 + cc * 16;
                cpasync16(colB + buf * 65536u + (unsigned)(sm * 8192 + r * 256 + cc * 16), src);
            }
            asm volatile("cp.async.commit_group;" ::: "memory");
        }

        const uint32_t BufC = colB + (unsigned)(it & 1) * 65536u;
#pragma unroll
        for (int sm = 0; sm < 2; sm++) {
            const int m = m0 + sm;
            // attn splats for this slot
            unsigned lo2[2], hi2[2];
            {
                unsigned pu;
                asm volatile("ld.shared.b32 %0, [%1];"
                             : "=r"(pu) : "r"(AP + (unsigned)(m * 56 + rowi * 8 + (l >> 2)) * 4));
                asm("prmt.b32 %0, %1, %1, 0x1010;" : "=r"(lo2[0]) : "r"(pu));
                asm("prmt.b32 %0, %1, %1, 0x3232;" : "=r"(hi2[0]) : "r"(pu));
            }
            if (has1) {
                unsigned pu;
                asm volatile("ld.shared.b32 %0, [%1];"
                             : "=r"(pu) : "r"(AP + (unsigned)(m * 56 + g1 * 8 + (l >> 2)) * 4));
                asm("prmt.b32 %0, %1, %1, 0x1010;" : "=r"(lo2[1]) : "r"(pu));
                asm("prmt.b32 %0, %1, %1, 0x3232;" : "=r"(hi2[1]) : "r"(pu));
            }

            const uint32_t Bb = BufC + (unsigned)(sm * 8192);
#pragma unroll
            for (int ks = 0; ks < 8; ks++) {
                const int c0 = ks * 2;
                unsigned bf[2][4];
                {
                    int n_off = ((l >> 4) << 3) + (l & 7);
                    int chB = c0 + ((l >> 3) & 1);
#pragma unroll
                    for (int np = 0; np < 2; np++) {
                        int rl = np * 16 + n_off;        // local row in strip
                        uint32_t addr = Bb + rl * 256 + ((chB ^ (rl & 7)) << 4);
                        ldsm4(bf[np], addr);
                    }
                }
                // group 0: hoisted A
                {
                    unsigned t[4];
                    t[0] = hmul2(Areg[ks][0], lo2[0]);
                    t[1] = hmul2(Areg[ks][1], hi2[0]);
                    t[2] = hmul2(Areg[ks][2], lo2[0]);
                    t[3] = hmul2(Areg[ks][3], hi2[0]);
#pragma unroll
                    for (int nt = 0; nt < 4; nt++)
                        mma16816(acc[0][nt], t, bf[nt >> 1][(nt & 1) * 2],
                                 bf[nt >> 1][(nt & 1) * 2 + 1]);
                }
                // group 1: per-slot ldsm from resident x tile
                if (has1) {
                    const int r_off = l & 15;
                    int chA = c0 + (l >> 4);
                    int row = g1 * 16 + r_off;
                    uint32_t addr = XS + row * 256 + ((chA ^ (r_off & 7)) << 4);
                    unsigned a[4];
                    ldsm4(a, addr);
                    unsigned t[4];
                    t[0] = hmul2(a[0], lo2[1]);
                    t[1] = hmul2(a[1], hi2[1]);
                    t[2] = hmul2(a[2], lo2[1]);
                    t[3] = hmul2(a[3], hi2[1]);
#pragma unroll
                    for (int nt = 0; nt < 4; nt++)
                        mma16816(acc[1][nt], t, bf[nt >> 1][(nt & 1) * 2],
                                 bf[nt >> 1][(nt & 1) * 2 + 1]);
                }
            }
        }
    }

    // ---- writeback ----
#pragma unroll
    for (int j = 0; j < 2; j++) {
        int g = rowi + 4 * j;
        if (j == 0 || has1) {
            int row = t0 + g * 16 + (l >> 2);
#pragma unroll
            for (int nt = 0; nt < 4; nt++) {
                int dcol = wd + nt * 8 + (l & 3) * 2;
                *(float2*)(out + (size_t)row * 128 + dcol) =
                    make_float2(acc[j][nt][0], acc[j][nt][1]);
                *(float2*)(out + (size_t)(row + 8) * 128 + dcol) =
                    make_float2(acc[j][nt][2], acc[j][nt][3]);
            }
        }
    }
}

// ---------------------------------------------------------------------------
extern "C" void kernel_launch(void* const* d_in, const int* in_sizes, int n_in,
                              void* d_out, int out_size) {
    const float* x   = (const float*)d_in[0];   // [4,4096,128]
    const float* MK  = (const float*)d_in[1];   // [64,128]
    const float* ops = (const float*)d_in[2];   // [64,128,128]
    const float* Wq  = (const float*)d_in[3];   // [128,128]
    const float* bq  = (const float*)d_in[4];   // [128]
    float* out = (float*)d_out;

    const int smem2 = 174080;
    cudaFuncSetAttribute(k2_fused, cudaFuncAttributeMaxDynamicSharedMemorySize, smem2);

    kA<<<576, 256>>>(ops, Wq, bq, MK);
    k2_fused<<<148, 512, smem2>>>(x, out);
}